// round 15
// baseline (speedup 1.0000x reference)
#include <cuda_runtime.h>

#define NATOMS_MAX 20000
#define NEDGES_MAX 500000
#define LOG2E 1.4426950408889634f
#define PI_OVER_CUT (3.14159265358979323846f / 6.0f)

// scratch (accumulators + packed edge records)
__device__ uint2 g_rec[NEDGES_MAX];        // {D, tgt|s<<20|t<<21}
__device__ float g_g2s[NATOMS_MAX * 16];   // [n][src_species][8 etas]
__device__ float g_g4s[NATOMS_MAX * 48];   // [n][t][ii*5+p] moments, 64B t-blocks

__device__ __forceinline__ float ex2(float x) {
    float y; asm("ex2.approx.ftz.f32 %0, %1;" : "=f"(y) : "f"(x)); return y;
}
__device__ __forceinline__ void red4(float* p, float a, float b, float c, float d) {
    asm volatile("red.global.add.v4.f32 [%0], {%1,%2,%3,%4};"
                 :: "l"(p), "f"(a), "f"(b), "f"(c), "f"(d) : "memory");
}
__device__ __forceinline__ float fc(float R) {
    return fmaf(0.5f, __cosf(PI_OVER_CUT * R), 0.5f);
}
__device__ __forceinline__ unsigned pk(int tgt, int s, int t) {
    return (unsigned)tgt | ((unsigned)s << 20) | ((unsigned)t << 21);
}

// k1: grid-stride prep. Stage an[] into smem as bytes (species lookups -> LDS pipe,
// off L1tex); then build packed edge records + zero accumulators, all coalesced.
__global__ void __launch_bounds__(256) prep_k(const int* __restrict__ an,
                                              const int* __restrict__ ei,
                                              const float* __restrict__ D,
                                              int E, int N) {
    __shared__ unsigned char s_an[NATOMS_MAX];
    for (int i = threadIdx.x; i < N; i += 256)
        s_an[i] = (unsigned char)__ldg(an + i);
    __syncthreads();

    int gstride = gridDim.x * 256;
    int g0 = blockIdx.x * 256 + threadIdx.x;

    // edge records: coalesced ei/D loads, LDS species lookups, coalesced 8B store
    for (int e = g0; e < E; e += gstride) {
        int src = __ldg(ei + e);
        int tgt = __ldg(ei + E + e);
        float d = __ldg(D + e);
        int s = s_an[src];
        int t = s_an[tgt];
        g_rec[e] = make_uint2(__float_as_uint(d), pk(tgt, s, t));
    }

    // zero accumulators (float4)
    float4 z = make_float4(0.f, 0.f, 0.f, 0.f);
    int n4g2 = N * 4;
    for (int i = g0; i < n4g2; i += gstride)
        reinterpret_cast<float4*>(g_g2s)[i] = z;
    int n4g4 = N * 12;
    for (int i = g0; i < n4g4; i += gstride)
        reinterpret_cast<float4*>(g_g4s)[i] = z;
}

// k2: heterogeneous blocks (R11 form) — [0, g4B): G4 triplets (moment scatter);
//     [g4B, g4B+g2B): G2 edges streaming packed records
__global__ void __launch_bounds__(256) fused_k(const int* __restrict__ id3_ba,
                                               const int* __restrict__ id3_ca,
                                               const float* __restrict__ cosphi,
                                               const float* __restrict__ g4_etas,
                                               const float* __restrict__ g2_etas,
                                               int T, int E, int g4B) {
    int b = blockIdx.x;
    if (b < g4B) {
        // ---- G4 path ----
        int i = b * 256 + threadIdx.x;
        if (i >= T) return;
        int ba = __ldg(id3_ba + i);
        int ca = __ldg(id3_ca + i);
        if (ba <= ca) return;                 // triplet dedup

        float cph = __ldg(cosphi + i);
        uint2 rb = g_rec[ba];
        uint2 rc = g_rec[ca];
        float Rba = __uint_as_float(rb.x);
        float Rca = __uint_as_float(rc.x);
        if (Rba >= 6.0f || Rca >= 6.0f) return;

        float Rbc2 = fmaf(Rba, Rba, fmaf(Rca, Rca, -2.0f * Rba * Rca * cph));
        float Rbc = sqrtf(fmaxf(Rbc2, 1e-12f));
        if (Rbc >= 6.0f) return;

        int aidx = rb.y & 0xFFFFF;
        int A    = (rb.y >> 21) & 1;          // central atom species
        int sb   = (rb.y >> 20) & 1;
        int sc   = (rc.y >> 20) & 1;
        int t = sb + sc;
        int k4 = A * 3 + t;

        float cut3 = fc(Rba) * fc(Rca) * fc(Rbc);
        float r2 = Rbc2 + Rba * Rba + Rca * Rca;

        const float* eta = g4_etas + k4 * 3;
        float mr2 = -r2 * LOG2E;
        float rad[3];
#pragma unroll
        for (int ii = 0; ii < 3; ii++) rad[ii] = ex2(mr2 * __ldg(eta + ii)) * cut3;

        float c1 = cph;
        float c2 = c1 * c1;
        float c3 = c2 * c1;
        float c4 = c2 * c2;
        float cp[5] = { 1.0f, c1, c2, c3, c4 };

        float v[15];
#pragma unroll
        for (int ii = 0; ii < 3; ii++)
#pragma unroll
            for (int p = 0; p < 5; p++)
                v[ii * 5 + p] = rad[ii] * cp[p];

        float* o = g_g4s + aidx * 48 + t * 16;   // 64B block: exactly 2 sectors
        red4(o,      v[0],  v[1],  v[2],  v[3]);
        red4(o + 4,  v[4],  v[5],  v[6],  v[7]);
        red4(o + 8,  v[8],  v[9],  v[10], v[11]);
        red4(o + 12, v[12], v[13], v[14], 0.0f);
    } else {
        // ---- G2 path: stream packed records, no random gathers ----
        int e = (b - g4B) * 256 + threadIdx.x;
        if (e >= E) return;
        uint2 r = g_rec[e];
        float d = __uint_as_float(r.x);
        int tgt = r.y & 0xFFFFF;
        int s   = (r.y >> 20) & 1;
        int t   = (r.y >> 21) & 1;

        float cut = fc(d);
        float md2 = -d * d * LOG2E;
        const float* eta = g2_etas + (s * 2 + t) * 8;
        float v[8];
#pragma unroll
        for (int k = 0; k < 8; k++) v[k] = cut * ex2(md2 * __ldg(eta + k));

        float* o = g_g2s + tgt * 16 + s * 8;
        red4(o,     v[0], v[1], v[2], v[3]);
        red4(o + 4, v[4], v[5], v[6], v[7]);
    }
}

// k3: reconstruct final [N,70]; one float2/thread; branch-free binomial reconstruction
__global__ void __launch_bounds__(256) combine_k(float2* __restrict__ out, int n2_total) {
    int i = blockIdx.x * blockDim.x + threadIdx.x;
    if (i >= n2_total) return;
    int n = i / 35;
    int c = (i - n * 35) * 2;   // even col; pair never spans g2/g4 boundary
    float2 v;
    if (c < 16) {
        const float* g2 = g_g2s + n * 16;
        v.x = g2[(c & 1) * 8 + (c >> 1)];
        v.y = g2[((c + 1) & 1) * 8 + ((c + 1) >> 1)];
    } else {
        const float* g4 = g_g4s + n * 48;
        float r[2];
#pragma unroll
        for (int q = 0; q < 2; q++) {
            int idx = c - 16 + q;          // idx = m*3 + t ; m = (ii*2+j)*3 + kk
            int t = idx % 3;
            int m = idx / 3;
            int ii = m / 6;
            int j  = (m / 3) & 1;          // lambda: 0 -> -1, 1 -> +1
            int kk = m % 3;                // zeta: 1, 2, 4
            const float* s = g4 + t * 16 + ii * 5;
            float S0 = s[0], S1 = s[1], S2 = s[2], S3 = s[3], S4 = s[4];
            float lS1 = j ? S1 : -S1;
            float lS3 = j ? S3 : -S3;
            float v1 = S0 + lS1;
            float v2 = 0.5f * fmaf(2.0f, lS1, S0 + S2);
            float v4 = 0.125f * (fmaf(6.0f, S2, S0 + S4) + 4.0f * (lS1 + lS3));
            r[q] = (kk == 0) ? v1 : ((kk == 1) ? v2 : v4);
        }
        v.x = r[0];
        v.y = r[1];
    }
    out[i] = v;
}

extern "C" void kernel_launch(void* const* d_in, const int* in_sizes, int n_in,
                              void* d_out, int out_size) {
    const int*   an       = (const int*)  d_in[0];
    const int*   ei       = (const int*)  d_in[1];
    const float* D        = (const float*)d_in[2];
    const int*   id3_ba   = (const int*)  d_in[3];
    const int*   id3_ca   = (const int*)  d_in[4];
    const float* cosphi   = (const float*)d_in[5];
    const float* g2_etas  = (const float*)d_in[6];
    const float* g4_etas  = (const float*)d_in[7];

    int E = in_sizes[2];
    int T = in_sizes[3];
    int N = in_sizes[0];

    // 4 blocks/SM x 152 SMs; 20KB static smem per block (80KB/SM, fits 228KB)
    prep_k<<<608, 256>>>(an, ei, D, E, N);

    int g4B = (T + 255) / 256;
    int g2B = (E + 255) / 256;
    fused_k<<<g4B + g2B, 256>>>(id3_ba, id3_ca, cosphi, g4_etas, g2_etas, T, E, g4B);

    int n2 = out_size / 2;
    combine_k<<<(n2 + 255) / 256, 256>>>((float2*)d_out, n2);
}

// round 17
// speedup vs baseline: 1.0727x; 1.0727x over previous
#include <cuda_runtime.h>

#define NATOMS_MAX 20000
#define NEDGES_MAX 500000
#define LOG2E 1.4426950408889634f
#define PI_OVER_CUT (3.14159265358979323846f / 6.0f)

// scratch (accumulators + packed edge records)
__device__ uint2 g_rec[NEDGES_MAX];        // {D, tgt|s<<20|t<<21}
__device__ float g_g2s[NATOMS_MAX * 16];   // [n][src_species][8 etas]
__device__ float g_g4s[NATOMS_MAX * 48];   // [n][t][ii*5+p] moments, 64B t-blocks

__device__ __forceinline__ float ex2(float x) {
    float y; asm("ex2.approx.ftz.f32 %0, %1;" : "=f"(y) : "f"(x)); return y;
}
__device__ __forceinline__ void red4(float* p, float a, float b, float c, float d) {
    asm volatile("red.global.add.v4.f32 [%0], {%1,%2,%3,%4};"
                 :: "l"(p), "f"(a), "f"(b), "f"(c), "f"(d) : "memory");
}
__device__ __forceinline__ float fc(float R) {
    return fmaf(0.5f, __cosf(PI_OVER_CUT * R), 0.5f);
}
__device__ __forceinline__ unsigned pk(int tgt, int s, int t) {
    return (unsigned)tgt | ((unsigned)s << 20) | ((unsigned)t << 21);
}

// k1: (R12 measured form) [0, recB): packed records, 2 edges/thread;
//     [recB, recB+zeroB): zero accumulators
__global__ void __launch_bounds__(256) rec_zero_k(const int* __restrict__ an,
                                                  const int* __restrict__ ei,
                                                  const float* __restrict__ D,
                                                  int E, int halfE, int recB, int N) {
    int b = blockIdx.x;
    if (b < recB) {
        int e0 = b * 256 + threadIdx.x;
        int e1 = e0 + halfE;
        bool p0 = e0 < halfE;
        bool p1 = e1 < E;
        int src0 = 0, tgt0 = 0, src1 = 0, tgt1 = 0;
        float d0 = 0.f, d1 = 0.f;
        if (p0) { src0 = __ldg(ei + e0); tgt0 = __ldg(ei + E + e0); d0 = __ldg(D + e0); }
        if (p1) { src1 = __ldg(ei + e1); tgt1 = __ldg(ei + E + e1); d1 = __ldg(D + e1); }
        int s0 = 0, t0 = 0, s1 = 0, t1 = 0;
        if (p0) { s0 = __ldg(an + src0); t0 = __ldg(an + tgt0); }
        if (p1) { s1 = __ldg(an + src1); t1 = __ldg(an + tgt1); }
        if (p0) g_rec[e0] = make_uint2(__float_as_uint(d0), pk(tgt0, s0, t0));
        if (p1) g_rec[e1] = make_uint2(__float_as_uint(d1), pk(tgt1, s1, t1));
    } else {
        int i = (b - recB) * 256 + threadIdx.x;
        float4 z = make_float4(0.f, 0.f, 0.f, 0.f);
        int n4g2 = N * 4;
        if (i < n4g2) reinterpret_cast<float4*>(g_g2s)[i] = z;
        int n4g4 = N * 12;
#pragma unroll
        for (int r = 0; r < 3; r++) {
            int j = i + r * n4g2;
            if (j < n4g4) reinterpret_cast<float4*>(g_g4s)[j] = z;
        }
    }
}

// ---- block bodies ----
__device__ __forceinline__ void g2_block(int k, int E,
                                         const float* __restrict__ g2_etas) {
    int e = k * 256 + threadIdx.x;
    if (e >= E) return;
    uint2 rr = g_rec[e];
    float d = __uint_as_float(rr.x);
    int tgt = rr.y & 0xFFFFF;
    int s   = (rr.y >> 20) & 1;
    int t   = (rr.y >> 21) & 1;

    float cut = fc(d);
    float md2 = -d * d * LOG2E;
    const float* eta = g2_etas + (s * 2 + t) * 8;
    float v[8];
#pragma unroll
    for (int kk = 0; kk < 8; kk++) v[kk] = cut * ex2(md2 * __ldg(eta + kk));

    float* o = g_g2s + tgt * 16 + s * 8;
    red4(o,     v[0], v[1], v[2], v[3]);
    red4(o + 4, v[4], v[5], v[6], v[7]);
}

__device__ __forceinline__ void g4_block(int i4, int T,
                                         const float* __restrict__ id3_ba,
                                         const float* __restrict__ id3_ca_f,
                                         const int* __restrict__ id3_ba_i,
                                         const int* __restrict__ id3_ca_i,
                                         const float* __restrict__ cosphi,
                                         const float* __restrict__ g4_etas) {
    int i = i4 * 256 + threadIdx.x;
    if (i >= T) return;
    int ba = __ldg(id3_ba_i + i);
    int ca = __ldg(id3_ca_i + i);
    if (ba <= ca) return;                 // triplet dedup

    float cph = __ldg(cosphi + i);
    uint2 rb = g_rec[ba];
    uint2 rc = g_rec[ca];
    float Rba = __uint_as_float(rb.x);
    float Rca = __uint_as_float(rc.x);
    if (Rba >= 6.0f || Rca >= 6.0f) return;

    float Rbc2 = fmaf(Rba, Rba, fmaf(Rca, Rca, -2.0f * Rba * Rca * cph));
    float Rbc = sqrtf(fmaxf(Rbc2, 1e-12f));
    if (Rbc >= 6.0f) return;

    int aidx = rb.y & 0xFFFFF;
    int A    = (rb.y >> 21) & 1;          // central atom species
    int sb   = (rb.y >> 20) & 1;
    int sc   = (rc.y >> 20) & 1;
    int t = sb + sc;
    int k4 = A * 3 + t;

    float cut3 = fc(Rba) * fc(Rca) * fc(Rbc);
    float r2 = Rbc2 + Rba * Rba + Rca * Rca;

    const float* eta = g4_etas + k4 * 3;
    float mr2 = -r2 * LOG2E;
    float rad[3];
#pragma unroll
    for (int ii = 0; ii < 3; ii++) rad[ii] = ex2(mr2 * __ldg(eta + ii)) * cut3;

    float c1 = cph;
    float c2 = c1 * c1;
    float c3 = c2 * c1;
    float c4 = c2 * c2;
    float cp[5] = { 1.0f, c1, c2, c3, c4 };

    float v[15];
#pragma unroll
    for (int ii = 0; ii < 3; ii++)
#pragma unroll
        for (int p = 0; p < 5; p++)
            v[ii * 5 + p] = rad[ii] * cp[p];

    float* o = g_g4s + aidx * 48 + t * 16;   // 64B block: exactly 2 sectors
    red4(o,      v[0],  v[1],  v[2],  v[3]);
    red4(o + 4,  v[4],  v[5],  v[6],  v[7]);
    red4(o + 8,  v[8],  v[9],  v[10], v[11]);
    red4(o + 12, v[12], v[13], v[14], 0.0f);
}

// k2: heterogeneous blocks with 4:1 interleaved roles. Bijective mapping:
//   b = 5k+4 with k < g2B                  -> g2 block k        (nslots of these)
//   else i4 = b - min((b+1)/5, g2B):
//       i4 <  g4B                          -> g4 block i4
//       i4 >= g4B (leftover, total%5 != 0) -> g2 block nslots + (i4 - g4B)
__global__ void __launch_bounds__(256) fused_k(const int* __restrict__ id3_ba,
                                               const int* __restrict__ id3_ca,
                                               const float* __restrict__ cosphi,
                                               const float* __restrict__ g4_etas,
                                               const float* __restrict__ g2_etas,
                                               int T, int E, int g4B, int g2B,
                                               int nslots) {
    int b = blockIdx.x;
    int k = b / 5;
    int r = b - k * 5;
    if (r == 4 && k < g2B) {
        g2_block(k, E, g2_etas);
        return;
    }
    int ng2_before = (b + 1) / 5;
    if (ng2_before > g2B) ng2_before = g2B;
    int i4 = b - ng2_before;
    if (i4 < g4B) {
        g4_block(i4, T, nullptr, nullptr, id3_ba, id3_ca, cosphi, g4_etas);
    } else {
        g2_block(nslots + (i4 - g4B), E, g2_etas);
    }
}

// k3: reconstruct final [N,70]; one float2/thread; branch-free binomial reconstruction
__global__ void __launch_bounds__(256) combine_k(float2* __restrict__ out, int n2_total) {
    int i = blockIdx.x * blockDim.x + threadIdx.x;
    if (i >= n2_total) return;
    int n = i / 35;
    int c = (i - n * 35) * 2;   // even col; pair never spans g2/g4 boundary
    float2 v;
    if (c < 16) {
        const float* g2 = g_g2s + n * 16;
        v.x = g2[(c & 1) * 8 + (c >> 1)];
        v.y = g2[((c + 1) & 1) * 8 + ((c + 1) >> 1)];
    } else {
        const float* g4 = g_g4s + n * 48;
        float r[2];
#pragma unroll
        for (int q = 0; q < 2; q++) {
            int idx = c - 16 + q;          // idx = m*3 + t ; m = (ii*2+j)*3 + kk
            int t = idx % 3;
            int m = idx / 3;
            int ii = m / 6;
            int j  = (m / 3) & 1;          // lambda: 0 -> -1, 1 -> +1
            int kk = m % 3;                // zeta: 1, 2, 4
            const float* s = g4 + t * 16 + ii * 5;
            float S0 = s[0], S1 = s[1], S2 = s[2], S3 = s[3], S4 = s[4];
            float lS1 = j ? S1 : -S1;
            float lS3 = j ? S3 : -S3;
            float v1 = S0 + lS1;
            float v2 = 0.5f * fmaf(2.0f, lS1, S0 + S2);
            float v4 = 0.125f * (fmaf(6.0f, S2, S0 + S4) + 4.0f * (lS1 + lS3));
            r[q] = (kk == 0) ? v1 : ((kk == 1) ? v2 : v4);
        }
        v.x = r[0];
        v.y = r[1];
    }
    out[i] = v;
}

extern "C" void kernel_launch(void* const* d_in, const int* in_sizes, int n_in,
                              void* d_out, int out_size) {
    const int*   an       = (const int*)  d_in[0];
    const int*   ei       = (const int*)  d_in[1];
    const float* D        = (const float*)d_in[2];
    const int*   id3_ba   = (const int*)  d_in[3];
    const int*   id3_ca   = (const int*)  d_in[4];
    const float* cosphi   = (const float*)d_in[5];
    const float* g2_etas  = (const float*)d_in[6];
    const float* g4_etas  = (const float*)d_in[7];

    int E = in_sizes[2];
    int T = in_sizes[3];
    int N = in_sizes[0];

    int halfE = (E + 1) / 2;
    int recB  = (halfE + 255) / 256;
    int zeroB = (N * 4 + 255) / 256;
    rec_zero_k<<<recB + zeroB, 256>>>(an, ei, D, E, halfE, recB, N);

    int g4B = (T + 255) / 256;
    int g2B = (E + 255) / 256;
    int total = g4B + g2B;
    // interleaved g2 slots: blocks b = 5k+4 < total with k < g2B
    int nslots = total >= 5 ? (total - 5) / 5 + 1 : 0;
    if (nslots > g2B) nslots = g2B;
    fused_k<<<total, 256>>>(id3_ba, id3_ca, cosphi, g4_etas, g2_etas,
                            T, E, g4B, g2B, nslots);

    int n2 = out_size / 2;
    combine_k<<<(n2 + 255) / 256, 256>>>((float2*)d_out, n2);
}